// round 11
// baseline (speedup 1.0000x reference)
#include <cuda_runtime.h>
#include <math.h>

#define BB 8
#define CC 19
#define HH 256
#define WW 256
#define HW (HH*WW)
#define NPIX (BB*HW)
#define INF_F 1e6f

// 2 threads cooperate on 4 pixels (channel split) -> NPIX/4*2 = 262144 threads
#define FBLK (NPIX / 512)   // 1024 blocks of 256

__device__ float g_g2[NPIX];      // squared row distance
__device__ float g_partial[FBLK];
__device__ int   g_count;         // zero-init at load; reset by last block

// ---------------------------------------------------------------------------
// Boundary detection (3x3 morphological gradient, edge padding) + exact
// per-row distance to nearest boundary column via bitmask + clz/ffs scan.
// One block per (b, h) row, 256 threads = one per column.
// ---------------------------------------------------------------------------
__global__ void k_boundary(const int* __restrict__ tgt) {
    int bh = blockIdx.x;
    int b  = bh >> 8;
    int h  = bh & 255;
    int j  = threadIdx.x;

    __shared__ int rows[3][WW];
    __shared__ unsigned mask[WW / 32];

    int hu = max(h - 1, 0), hd = min(h + 1, HH - 1);
    const int* base = tgt + b * HW;
    rows[0][j] = base[hu * WW + j];
    rows[1][j] = base[h  * WW + j];
    rows[2][j] = base[hd * WW + j];
    __syncthreads();

    int jl = max(j - 1, 0), jr = min(j + 1, WW - 1);
    int v0 = rows[0][jl], v1 = rows[0][j], v2 = rows[0][jr];
    int v3 = rows[1][jl], v4 = rows[1][j], v5 = rows[1][jr];
    int v6 = rows[2][jl], v7 = rows[2][j], v8 = rows[2][jr];
    int mn = min(min(min(v0, v1), min(v2, v3)), min(min(v4, v5), min(min(v6, v7), v8)));
    int mx = max(max(max(v0, v1), max(v2, v3)), max(max(v4, v5), max(max(v6, v7), v8)));
    bool bd = (mx != mn);

    unsigned bal = __ballot_sync(0xffffffffu, bd);
    if ((j & 31) == 0) mask[j >> 5] = bal;
    __syncthreads();

    int wj = j >> 5, bj = j & 31;
    int dist = 0x7fffffff;

    {   // left
        unsigned m = mask[wj] & (0xffffffffu >> (31 - bj));
        int w = wj;
        for (;;) {
            if (m) { int pos = (w << 5) + 31 - __clz(m); dist = min(dist, j - pos); break; }
            if (--w < 0) break;
            m = mask[w];
        }
    }
    {   // right
        unsigned m = mask[wj] & (0xffffffffu << bj);
        int w = wj;
        for (;;) {
            if (m) { int pos = (w << 5) + __ffs(m) - 1; dist = min(dist, pos - j); break; }
            if (++w >= WW / 32) break;
            m = mask[w];
        }
    }

    float g = (dist == 0x7fffffff) ? INF_F : (float)dist;
    g_g2[b * HW + h * WW + j] = g * g;
}

// ---------------------------------------------------------------------------
// Fused CE + EDT. Thread pairs cooperate on a 4-pixel group:
//   even lane: channels 0..9, odd lane: channels 10..18 (float4 LDG.128 each)
//   -> ~10 LDG/thread instead of 22 (LSU-issue relief), same 8192 warps.
// Partial sum-exp / target-logit combined via shfl_xor(1). Each pair member
// then does the EDT ring + weight + accumulate for 2 of the 4 pixels.
// ---------------------------------------------------------------------------
__global__ void __launch_bounds__(256, 7) k_fused(const float* __restrict__ x,
                                                  const int* __restrict__ tgt,
                                                  float* __restrict__ out) {
    int tid = threadIdx.x;
    int t = blockIdx.x * 256 + tid;
    int g = t >> 1;                   // 4-pixel group index
    int hf = t & 1;                   // which channel half
    int p = g * 4;                    // first pixel of group
    int b = p >> 16;                  // p / HW
    int rem = p & (HW - 1);
    int i = rem >> 8;                 // row (quad shares row)

    const float4* px = (const float4*)(x + (size_t)b * CC * HW + rem);
    int4 tg = *(const int4*)(tgt + p);

    float s0 = 0.f, s1 = 0.f, s2 = 0.f, s3 = 0.f;
    float xt0 = 0.f, xt1 = 0.f, xt2 = 0.f, xt3 = 0.f;
    int cbase = hf * 10;
    #pragma unroll
    for (int k = 0; k < 10; k++) {
        int c = cbase + k;
        if (c < CC) {
            float4 vv = px[c * (HW / 4)];
            s0 += __expf(vv.x);
            s1 += __expf(vv.y);
            s2 += __expf(vv.z);
            s3 += __expf(vv.w);
            if (c == tg.x) xt0 = vv.x;
            if (c == tg.y) xt1 = vv.y;
            if (c == tg.z) xt2 = vv.z;
            if (c == tg.w) xt3 = vv.w;
        }
    }
    // combine halves across the thread pair
    s0 += __shfl_xor_sync(0xffffffffu, s0, 1);
    s1 += __shfl_xor_sync(0xffffffffu, s1, 1);
    s2 += __shfl_xor_sync(0xffffffffu, s2, 1);
    s3 += __shfl_xor_sync(0xffffffffu, s3, 1);
    xt0 += __shfl_xor_sync(0xffffffffu, xt0, 1);
    xt1 += __shfl_xor_sync(0xffffffffu, xt1, 1);
    xt2 += __shfl_xor_sync(0xffffffffu, xt2, 1);
    xt3 += __shfl_xor_sync(0xffffffffu, xt3, 1);

    // this thread finalizes 2 of the 4 pixels
    float sa  = hf ? s2  : s0,  sb  = hf ? s3  : s1;
    float xta = hf ? xt2 : xt0, xtb = hf ? xt3 : xt1;
    float cea = __logf(sa) - xta;
    float ceb = __logf(sb) - xtb;

    // ---- column EDT: d^2(i,j) = min_k (i-k)^2 + g2(k,j), expanding ring ----
    const float4* g2b = (const float4*)(g_g2 + (size_t)b * HW);
    int colidx = (rem & 255) >> 2;    // float4 column within row
    float4 cg = g2b[i * (WW / 4) + colidx];
    float ca = hf ? cg.z : cg.x;
    float cb = hf ? cg.w : cg.y;

    for (int r = 1; r < HH; r++) {
        float r2 = (float)(r * r);
        if (r2 >= fmaxf(ca, cb)) break;
        int lo = i - r, hi = i + r;
        if (lo >= 0) {
            float4 nb = g2b[lo * (WW / 4) + colidx];
            float na = hf ? nb.z : nb.x, nb2 = hf ? nb.w : nb.y;
            ca = fminf(ca, r2 + na); cb = fminf(cb, r2 + nb2);
        }
        if (hi < HH) {
            float4 nb = g2b[hi * (WW / 4) + colidx];
            float na = hf ? nb.z : nb.x, nb2 = hf ? nb.w : nb.y;
            ca = fminf(ca, r2 + na); cb = fminf(cb, r2 + nb2);
        }
    }

    // No boundary in image b  =>  d^2 >= INF^2 = 1e12  =>  weight 1.
    float wa = (ca >= 1e11f) ? 1.0f : __expf(-sqrtf(ca) * 0.2f);
    float wb = (cb >= 1e11f) ? 1.0f : __expf(-sqrtf(cb) * 0.2f);
    float acc = wa * cea + wb * ceb;

    // block reduction
    __shared__ float red[8];
    #pragma unroll
    for (int o = 16; o > 0; o >>= 1) acc += __shfl_down_sync(0xffffffffu, acc, o);
    if ((tid & 31) == 0) red[tid >> 5] = acc;
    __syncthreads();
    if (tid == 0) {
        float s = red[0];
        #pragma unroll
        for (int w = 1; w < 8; w++) s += red[w];
        g_partial[blockIdx.x] = s;
    }

    // last-block final reduction (deterministic fixed-order sum)
    __shared__ int isLast;
    if (tid == 0) {
        __threadfence();
        int old = atomicAdd(&g_count, 1);
        isLast = (old == FBLK - 1);
    }
    __syncthreads();
    if (isLast) {
        float s = 0.f;
        #pragma unroll
        for (int k = 0; k < 4; k++) s += g_partial[tid + k * 256];
        __shared__ float fr[8];
        #pragma unroll
        for (int o = 16; o > 0; o >>= 1) s += __shfl_down_sync(0xffffffffu, s, o);
        if ((tid & 31) == 0) fr[tid >> 5] = s;
        __syncthreads();
        if (tid == 0) {
            float tot = fr[0];
            #pragma unroll
            for (int w = 1; w < 8; w++) tot += fr[w];
            out[0] = tot * (1.0f / (float)NPIX);
            g_count = 0;   // reset for next graph replay
        }
    }
}

extern "C" void kernel_launch(void* const* d_in, const int* in_sizes, int n_in,
                              void* d_out, int out_size) {
    const float* x   = (const float*)d_in[0];
    const int*   tgt = (const int*)d_in[1];
    float* out = (float*)d_out;

    k_boundary<<<BB * HH, WW>>>(tgt);
    k_fused<<<FBLK, 256>>>(x, tgt, out);
}